// round 15
// baseline (speedup 1.0000x reference)
#include <cuda_runtime.h>
#include <cuda_bf16.h>
#include <cuda_fp16.h>
#include <math.h>
#include <stdint.h>

#define N_ENT  50000
#define NDIM   256
#define BSZ    1024
#define M_ROWS 2048
#define NPAD   50048          // 391 * 128
#define N_PAD_COLS (NPAD - N_ENT)   // 48, deterministic s=0 columns
#define CONV_BLOCKS 6256

// ---------------- device scratch ----------------
__device__ float          g_scale[768];
__device__ float          g_shift[768];
__device__ __nv_bfloat16  g_Vhi[M_ROWS * NDIM];
__device__ __nv_bfloat16  g_Ehi[(size_t)NPAD * NDIM];
__device__ float          g_L1[M_ROWS];
__device__ float          g_sy[M_ROWS];
__device__ double         g_acc;

// ---------------- PTX helpers (sm_103-base-safe) ----------------
__device__ __forceinline__ uint32_t smem_to_u32(const void* p) {
    uint32_t a;
    asm("{ .reg .u64 t; cvta.to.shared.u64 t, %1; cvt.u32.u64 %0, t; }" : "=r"(a) : "l"(p));
    return a;
}
__device__ __forceinline__ void cp16(uint32_t s, const void* g) {
    asm volatile("cp.async.cg.shared.global [%0], [%1], 16;" :: "r"(s), "l"(g) : "memory");
}
__device__ __forceinline__ void cp_commit() {
    asm volatile("cp.async.commit_group;" ::: "memory");
}
template <int N>
__device__ __forceinline__ void cp_wait() {
    asm volatile("cp.async.wait_group %0;" :: "n"(N) : "memory");
}
__device__ __forceinline__ void ldsm_x4(uint32_t* r, uint32_t a) {
    asm volatile("ldmatrix.sync.aligned.m8n8.x4.shared.b16 {%0,%1,%2,%3}, [%4];"
                 : "=r"(r[0]), "=r"(r[1]), "=r"(r[2]), "=r"(r[3]) : "r"(a));
}
__device__ __forceinline__ void mma16816(float* c, const uint32_t* a, uint32_t b0, uint32_t b1) {
    asm volatile("mma.sync.aligned.m16n8k16.row.col.f32.bf16.bf16.f32 "
                 "{%0,%1,%2,%3}, {%4,%5,%6,%7}, {%8,%9}, {%0,%1,%2,%3};"
                 : "+f"(c[0]), "+f"(c[1]), "+f"(c[2]), "+f"(c[3])
                 : "r"(a[0]), "r"(a[1]), "r"(a[2]), "r"(a[3]), "r"(b0), "r"(b1));
}

// ---------------- kernel 1: fused ent_w->bf16 convert + BN statistics -------
__global__ void prep_kernel(const int* __restrict__ facts,
                            const float* __restrict__ ent_w,
                            const float* __restrict__ rel_w,
                            const float* __restrict__ bg_e,
                            const float* __restrict__ bb_e,
                            const float* __restrict__ bg_r,
                            const float* __restrict__ bb_r) {
    int tid = threadIdx.x;
    if (blockIdx.x < CONV_BLOCKS) {
        int t = blockIdx.x * 256 + tid;
        int row = t >> 5;
        int k8  = (t & 31) * 8;
        float v[8];
        if (row < N_ENT) {
            float4 a = *(const float4*)&ent_w[(size_t)row * NDIM + k8];
            float4 b = *(const float4*)&ent_w[(size_t)row * NDIM + k8 + 4];
            v[0] = a.x; v[1] = a.y; v[2] = a.z; v[3] = a.w;
            v[4] = b.x; v[5] = b.y; v[6] = b.z; v[7] = b.w;
        } else {
#pragma unroll
            for (int i = 0; i < 8; i++) v[i] = 0.f;
        }
        __align__(16) __nv_bfloat16 hb[8];
#pragma unroll
        for (int i = 0; i < 8; i++) hb[i] = __float2bfloat16(v[i]);
        *(uint4*)&g_Ehi[(size_t)row * NDIM + k8] = *(uint4*)hb;
        return;
    }
    int sub = blockIdx.x - CONV_BLOCKS;      // 0..767
    if (sub == 0 && tid == 0) g_acc = 0.0;   // zero loss accumulator
    int s = sub >> 8, d = sub & 255;
    const float* W = (s == 2) ? rel_w : ent_w;
    float sum = 0.f, sq = 0.f;
    for (int b = tid; b < BSZ; b += 256) {
        int idx = facts[b * 3 + s];
        float x = W[idx * NDIM + d];
        sum += x; sq += x * x;
    }
    __shared__ float s1[256], s2[256];
    s1[tid] = sum; s2[tid] = sq; __syncthreads();
    for (int o = 128; o > 0; o >>= 1) {
        if (tid < o) { s1[tid] += s1[tid + o]; s2[tid] += s2[tid + o]; }
        __syncthreads();
    }
    if (tid == 0) {
        float mean = s1[0] * (1.f / BSZ);
        float var  = s2[0] * (1.f / BSZ) - mean * mean;
        float gamma = (s == 2) ? bg_r[d] : bg_e[d];
        float beta  = (s == 2) ? bb_r[d] : bb_e[d];
        float sc = gamma * rsqrtf(var + 1e-5f);
        g_scale[s * 256 + d] = sc;
        g_shift[s * 256 + d] = beta - mean * sc;
    }
}

// ---------------- kernel 2: vectors + label scores + L1 zero (fused) --------
__global__ void build_vec_kernel(const int* __restrict__ facts,
                                 const int* __restrict__ arch,
                                 const float* __restrict__ ent_w,
                                 const float* __restrict__ rel_w) {
    int b = blockIdx.x, tid = threadIdx.x;
    __shared__ float hen[256], ten[256], ren[256], al[64], red[256];
    int h = facts[3 * b], t = facts[3 * b + 1], r = facts[3 * b + 2];
    hen[tid] = ent_w[h * NDIM + tid] * g_scale[tid]       + g_shift[tid];
    ten[tid] = ent_w[t * NDIM + tid] * g_scale[256 + tid] + g_shift[256 + tid];
    ren[tid] = rel_w[r * NDIM + tid] * g_scale[512 + tid] + g_shift[512 + tid];
    if (tid < 64) {
        int a = arch[tid];
        al[tid] = (a == 1) ? 1.f : ((a == 2) ? -1.f : 0.f);
    }
    __syncthreads();
    int k = tid >> 6, l = tid & 63;
    float hv = 0.f, tv = 0.f;
#pragma unroll
    for (int i = 0; i < 4; i++) {
        float rv = ren[i * 64 + l];
#pragma unroll
        for (int j = 0; j < 4; j++) {
            hv += al[i * 16 + j * 4 + k] * rv * ten[j * 64 + l];
            tv += al[i * 16 + k * 4 + j] * rv * hen[j * 64 + l];
        }
    }
    g_Vhi[b * NDIM + tid]         = __float2bfloat16(hv);
    g_Vhi[(BSZ + b) * NDIM + tid] = __float2bfloat16(tv);

    float eh = __bfloat162float(g_Ehi[(size_t)h * NDIM + tid]);
    float et = __bfloat162float(g_Ehi[(size_t)t * NDIM + tid]);
    red[tid] = hv * eh; __syncthreads();
    for (int o = 128; o > 0; o >>= 1) {
        if (tid < o) red[tid] += red[tid + o];
        __syncthreads();
    }
    if (tid == 0) g_sy[b] = red[0];
    __syncthreads();
    red[tid] = tv * et; __syncthreads();
    for (int o = 128; o > 0; o >>= 1) {
        if (tid < o) red[tid] += red[tid + o];
        __syncthreads();
    }
    if (tid == 0) {
        g_sy[BSZ + b] = red[0];
        g_L1[b] = 0.f; g_L1[BSZ + b] = 0.f;
    }
}

// ---------------- kernel 3: bf16 HMMA GEMM + fused L1 epilogue --------------
// BM=128, BN=128. A tile (128x256 = 64KB) loaded ONCE; B triple-buffered
// (3 x 16KB, BK=64) -> 112KB/CTA, 2 CTAs/SM. 8 warps (4m x 2n), warp 32x64.
#define SMEM_A_BYTES   65536
#define SMEM_B_STAGE   16384
#define SMEM_TOTAL_GEMM (SMEM_A_BYTES + 3 * SMEM_B_STAGE)   // 112KB
#define SHIFT16_LOG2 23.083120654223414f   // 16 * log2(e)
#define LOG2E        1.44269504088896f

__global__ __launch_bounds__(256, 2) void gemm_kernel() {
    extern __shared__ __align__(128) char smem[];
    uint32_t sbase = smem_to_u32(smem);
    int tid = threadIdx.x, lane = tid & 31, w = tid >> 5;
    int n0g = blockIdx.x * 128, m0 = blockIdx.y * 128;
    int wm = w >> 1, wn = w & 1;

    float acc[2][8][4];
#pragma unroll
    for (int i = 0; i < 2; i++)
#pragma unroll
        for (int j = 0; j < 8; j++)
#pragma unroll
            for (int q = 0; q < 4; q++) acc[i][j][q] = 0.f;

    // ---- prologue: full A tile (128 rows x 32 16B-chunks) + B stages 0..2
    {
#pragma unroll
        for (int i = 0; i < 16; i++) {
            int c = tid + i * 256;            // 0..4095
            int row = c >> 5, pos = c & 31;
            uint32_t off = (uint32_t)(row * 512 + ((pos ^ (row & 7)) << 4));
            cp16(sbase + off, g_Vhi + (size_t)(m0 + row) * NDIM + pos * 8);
        }
    }
    int b_row[4], b_pos[4]; uint32_t b_soff[4];
#pragma unroll
    for (int i = 0; i < 4; i++) {
        int c = tid + i * 256;                // 0..1023
        b_row[i] = c >> 3;
        b_pos[i] = c & 7;
        b_soff[i] = (uint32_t)(b_row[i] * 128 + ((b_pos[i] ^ (b_row[i] & 7)) << 4));
    }
    auto load_B = [&](int kt, int s) {
        int kk = kt * 64;
        uint32_t sB = sbase + SMEM_A_BYTES + (uint32_t)s * SMEM_B_STAGE;
#pragma unroll
        for (int i = 0; i < 4; i++)
            cp16(sB + b_soff[i], g_Ehi + (size_t)(n0g + b_row[i]) * NDIM + kk + b_pos[i] * 8);
        cp_commit();
    };
    load_B(0, 0);   // group 0 (with A)
    load_B(1, 1);   // group 1
    load_B(2, 2);   // group 2

    for (int kt = 0; kt < 4; kt++) {
        int s = kt % 3;
        if (kt <= 1) cp_wait<2>();
        else if (kt == 2) cp_wait<1>();
        else cp_wait<0>();
        __syncthreads();

        uint32_t sB = sbase + SMEM_A_BYTES + (uint32_t)s * SMEM_B_STAGE;
#pragma unroll
        for (int ks = 0; ks < 4; ks++) {
            uint32_t br[4][4];
#pragma unroll
            for (int nb = 0; nb < 4; nb++) {
                int n = wn * 64 + nb * 16 + (lane & 7) + ((lane >> 4) & 1) * 8;
                int chunk = ks * 2 + ((lane >> 3) & 1);
                ldsm_x4(br[nb], sB + (uint32_t)(n * 128 + ((chunk ^ (n & 7)) << 4)));
            }
            uint32_t ar[2][4];
#pragma unroll
            for (int mf = 0; mf < 2; mf++) {
                int row = wm * 32 + mf * 16 + (lane & 15);
                int chunk = kt * 8 + ks * 2 + (lane >> 4);
                ldsm_x4(ar[mf], sbase + (uint32_t)(row * 512 + ((chunk ^ (row & 7)) << 4)));
            }
#pragma unroll
            for (int mf = 0; mf < 2; mf++)
#pragma unroll
                for (int nb = 0; nb < 4; nb++) {
                    mma16816(acc[mf][nb * 2],     ar[mf], br[nb][0], br[nb][1]);
                    mma16816(acc[mf][nb * 2 + 1], ar[mf], br[nb][2], br[nb][3]);
                }
        }
        // only kt==0 overwrites a stage afterwards -> barrier only there
        if (kt == 0) {
            __syncthreads();
            load_B(3, 0);   // refill stage 0 with the last tile
        }
    }

    // ---- fused epilogue: per-row L1, all-MUFU exp ----
#pragma unroll
    for (int mf = 0; mf < 2; mf++) {
#pragma unroll
        for (int half = 0; half < 2; half++) {
            float a1 = 0.f;
#pragma unroll
            for (int nf = 0; nf < 8; nf++) {
                a1 += exp2f(fmaf(acc[mf][nf][half * 2],     LOG2E, -SHIFT16_LOG2));
                a1 += exp2f(fmaf(acc[mf][nf][half * 2 + 1], LOG2E, -SHIFT16_LOG2));
            }
            a1 += __shfl_xor_sync(0xffffffffu, a1, 1);
            a1 += __shfl_xor_sync(0xffffffffu, a1, 2);
            if ((lane & 3) == 0) {
                int row = m0 + wm * 32 + mf * 16 + half * 8 + (lane >> 2);
                atomicAdd(&g_L1[row], a1);
            }
        }
    }
}

// ---------------- kernel 4: finalize, 8 blocks x 256 (1 row/thread) ---------
__global__ void finalize_kernel() {
    int r = blockIdx.x * 256 + threadIdx.x;
    int tid = threadIdx.x;
    float padL1 = (float)N_PAD_COLS * exp2f(-SHIFT16_LOG2);
    float L1 = g_L1[r] - padL1;
    float lse = 16.f + logf(L1);
    float dy = g_sy[r] - lse;
    float logp = fmaxf(dy, -100.f);
    float py = __expf(dy);
    float lm_y = fmaxf(log1pf(-py), -100.f);
    double acc = (double)(-1.f) + (double)logp - (double)lm_y;

    __shared__ double rd[256];
    rd[tid] = acc; __syncthreads();
    for (int o = 128; o > 0; o >>= 1) {
        if (tid < o) rd[tid] += rd[tid + o];
        __syncthreads();
    }
    if (tid == 0) atomicAdd(&g_acc, rd[0]);
}

// ---------------- kernel 5: write output ------------------------------------
__global__ void write_kernel(float* out) {
    out[0] = (float)(-g_acc * (1.0 / ((double)BSZ * (double)N_ENT)));
}

// ---------------- launch ----------------------------------------------------
extern "C" void kernel_launch(void* const* d_in, const int* in_sizes, int n_in,
                              void* d_out, int out_size) {
    const int*   facts = (const int*)d_in[0];
    const int*   arch  = (const int*)d_in[1];
    const float* ent_w = (const float*)d_in[2];
    const float* rel_w = (const float*)d_in[3];
    const float* bg_e  = (const float*)d_in[4];
    const float* bb_e  = (const float*)d_in[5];
    const float* bg_r  = (const float*)d_in[6];
    const float* bb_r  = (const float*)d_in[7];
    float* out = (float*)d_out;

    cudaFuncSetAttribute(gemm_kernel, cudaFuncAttributeMaxDynamicSharedMemorySize,
                         SMEM_TOTAL_GEMM);

    prep_kernel<<<CONV_BLOCKS + 768, 256>>>(facts, ent_w, rel_w, bg_e, bb_e, bg_r, bb_r);
    build_vec_kernel<<<BSZ, 256>>>(facts, arch, ent_w, rel_w);
    gemm_kernel<<<dim3(NPAD / 128, M_ROWS / 128), 256, SMEM_TOTAL_GEMM>>>();
    finalize_kernel<<<8, 256>>>();
    write_kernel<<<1, 1>>>(out);
}

// round 17
// speedup vs baseline: 1.0830x; 1.0830x over previous
#include <cuda_runtime.h>
#include <cuda_bf16.h>
#include <cuda_fp16.h>
#include <math.h>
#include <stdint.h>

#define N_ENT  50000
#define NDIM   256
#define BSZ    1024
#define M_ROWS 2048
#define NPAD   50048          // 391 * 128
#define N_PAD_COLS (NPAD - N_ENT)   // 48, deterministic s=0 columns
#define CONV_BLOCKS 6256

// ---------------- device scratch ----------------
__device__ float          g_scale[768];
__device__ float          g_shift[768];
__device__ __nv_bfloat16  g_Vhi[M_ROWS * NDIM];
__device__ __nv_bfloat16  g_Ehi[(size_t)NPAD * NDIM];
__device__ float          g_L1[M_ROWS];
__device__ float          g_sy[M_ROWS];
__device__ double         g_acc;

// ---------------- PTX helpers (sm_103-base-safe) ----------------
__device__ __forceinline__ uint32_t smem_to_u32(const void* p) {
    uint32_t a;
    asm("{ .reg .u64 t; cvta.to.shared.u64 t, %1; cvt.u32.u64 %0, t; }" : "=r"(a) : "l"(p));
    return a;
}
__device__ __forceinline__ void cp16(uint32_t s, const void* g) {
    asm volatile("cp.async.cg.shared.global [%0], [%1], 16;" :: "r"(s), "l"(g) : "memory");
}
__device__ __forceinline__ void cp_commit() {
    asm volatile("cp.async.commit_group;" ::: "memory");
}
template <int N>
__device__ __forceinline__ void cp_wait() {
    asm volatile("cp.async.wait_group %0;" :: "n"(N) : "memory");
}
__device__ __forceinline__ void ldsm_x4(uint32_t* r, uint32_t a) {
    asm volatile("ldmatrix.sync.aligned.m8n8.x4.shared.b16 {%0,%1,%2,%3}, [%4];"
                 : "=r"(r[0]), "=r"(r[1]), "=r"(r[2]), "=r"(r[3]) : "r"(a));
}
__device__ __forceinline__ void mma16816(float* c, const uint32_t* a, uint32_t b0, uint32_t b1) {
    asm volatile("mma.sync.aligned.m16n8k16.row.col.f32.bf16.bf16.f32 "
                 "{%0,%1,%2,%3}, {%4,%5,%6,%7}, {%8,%9}, {%0,%1,%2,%3};"
                 : "+f"(c[0]), "+f"(c[1]), "+f"(c[2]), "+f"(c[3])
                 : "r"(a[0]), "r"(a[1]), "r"(a[2]), "r"(a[3]), "r"(b0), "r"(b1));
}

// ---------------- kernel 1: fused ent_w->bf16 convert + BN statistics -------
__global__ void prep_kernel(const int* __restrict__ facts,
                            const float* __restrict__ ent_w,
                            const float* __restrict__ rel_w,
                            const float* __restrict__ bg_e,
                            const float* __restrict__ bb_e,
                            const float* __restrict__ bg_r,
                            const float* __restrict__ bb_r) {
    int tid = threadIdx.x;
    if (blockIdx.x < CONV_BLOCKS) {
        int t = blockIdx.x * 256 + tid;
        int row = t >> 5;
        int k8  = (t & 31) * 8;
        float v[8];
        if (row < N_ENT) {
            float4 a = *(const float4*)&ent_w[(size_t)row * NDIM + k8];
            float4 b = *(const float4*)&ent_w[(size_t)row * NDIM + k8 + 4];
            v[0] = a.x; v[1] = a.y; v[2] = a.z; v[3] = a.w;
            v[4] = b.x; v[5] = b.y; v[6] = b.z; v[7] = b.w;
        } else {
#pragma unroll
            for (int i = 0; i < 8; i++) v[i] = 0.f;
        }
        __align__(16) __nv_bfloat16 hb[8];
#pragma unroll
        for (int i = 0; i < 8; i++) hb[i] = __float2bfloat16(v[i]);
        *(uint4*)&g_Ehi[(size_t)row * NDIM + k8] = *(uint4*)hb;
        return;
    }
    int sub = blockIdx.x - CONV_BLOCKS;      // 0..767
    if (sub == 0 && tid == 0) g_acc = 0.0;   // zero loss accumulator
    int s = sub >> 8, d = sub & 255;
    const float* W = (s == 2) ? rel_w : ent_w;
    float sum = 0.f, sq = 0.f;
    for (int b = tid; b < BSZ; b += 256) {
        int idx = facts[b * 3 + s];
        float x = W[idx * NDIM + d];
        sum += x; sq += x * x;
    }
    __shared__ float s1[256], s2[256];
    s1[tid] = sum; s2[tid] = sq; __syncthreads();
    for (int o = 128; o > 0; o >>= 1) {
        if (tid < o) { s1[tid] += s1[tid + o]; s2[tid] += s2[tid + o]; }
        __syncthreads();
    }
    if (tid == 0) {
        float mean = s1[0] * (1.f / BSZ);
        float var  = s2[0] * (1.f / BSZ) - mean * mean;
        float gamma = (s == 2) ? bg_r[d] : bg_e[d];
        float beta  = (s == 2) ? bb_r[d] : bb_e[d];
        float sc = gamma * rsqrtf(var + 1e-5f);
        g_scale[s * 256 + d] = sc;
        g_shift[s * 256 + d] = beta - mean * sc;
    }
}

// ---------------- kernel 2: vectors + label scores + L1 zero (fused) --------
__global__ void build_vec_kernel(const int* __restrict__ facts,
                                 const int* __restrict__ arch,
                                 const float* __restrict__ ent_w,
                                 const float* __restrict__ rel_w) {
    int b = blockIdx.x, tid = threadIdx.x;
    __shared__ float hen[256], ten[256], ren[256], al[64], red[256];
    int h = facts[3 * b], t = facts[3 * b + 1], r = facts[3 * b + 2];
    hen[tid] = ent_w[h * NDIM + tid] * g_scale[tid]       + g_shift[tid];
    ten[tid] = ent_w[t * NDIM + tid] * g_scale[256 + tid] + g_shift[256 + tid];
    ren[tid] = rel_w[r * NDIM + tid] * g_scale[512 + tid] + g_shift[512 + tid];
    if (tid < 64) {
        int a = arch[tid];
        al[tid] = (a == 1) ? 1.f : ((a == 2) ? -1.f : 0.f);
    }
    __syncthreads();
    int k = tid >> 6, l = tid & 63;
    float hv = 0.f, tv = 0.f;
#pragma unroll
    for (int i = 0; i < 4; i++) {
        float rv = ren[i * 64 + l];
#pragma unroll
        for (int j = 0; j < 4; j++) {
            hv += al[i * 16 + j * 4 + k] * rv * ten[j * 64 + l];
            tv += al[i * 16 + k * 4 + j] * rv * hen[j * 64 + l];
        }
    }
    g_Vhi[b * NDIM + tid]         = __float2bfloat16(hv);
    g_Vhi[(BSZ + b) * NDIM + tid] = __float2bfloat16(tv);

    float eh = __bfloat162float(g_Ehi[(size_t)h * NDIM + tid]);
    float et = __bfloat162float(g_Ehi[(size_t)t * NDIM + tid]);
    red[tid] = hv * eh; __syncthreads();
    for (int o = 128; o > 0; o >>= 1) {
        if (tid < o) red[tid] += red[tid + o];
        __syncthreads();
    }
    if (tid == 0) g_sy[b] = red[0];
    __syncthreads();
    red[tid] = tv * et; __syncthreads();
    for (int o = 128; o > 0; o >>= 1) {
        if (tid < o) red[tid] += red[tid + o];
        __syncthreads();
    }
    if (tid == 0) {
        g_sy[BSZ + b] = red[0];
        g_L1[b] = 0.f; g_L1[BSZ + b] = 0.f;
    }
}

// ---------------- kernel 3: bf16 HMMA GEMM + fused L1 epilogue --------------
// BM=128, BN=128. A tile (128x256 = 64KB) loaded ONCE; B triple-buffered
// (3 x 16KB, BK=64) -> 112KB/CTA, 2 CTAs/SM. 8 warps (4m x 2n), warp 32x64.
// R14 barrier structure restored (bottom __syncthreads every kt).
#define SMEM_A_BYTES   65536
#define SMEM_B_STAGE   16384
#define SMEM_TOTAL_GEMM (SMEM_A_BYTES + 3 * SMEM_B_STAGE)   // 112KB
#define SHIFT16_LOG2 23.083120654223414f   // 16 * log2(e)
#define LOG2E        1.44269504088896f

__global__ __launch_bounds__(256, 2) void gemm_kernel() {
    extern __shared__ __align__(128) char smem[];
    uint32_t sbase = smem_to_u32(smem);
    int tid = threadIdx.x, lane = tid & 31, w = tid >> 5;
    int n0g = blockIdx.x * 128, m0 = blockIdx.y * 128;
    int wm = w >> 1, wn = w & 1;

    float acc[2][8][4];
#pragma unroll
    for (int i = 0; i < 2; i++)
#pragma unroll
        for (int j = 0; j < 8; j++)
#pragma unroll
            for (int q = 0; q < 4; q++) acc[i][j][q] = 0.f;

    // ---- prologue: full A tile (128 rows x 32 16B-chunks) + B stages 0..2
    {
#pragma unroll
        for (int i = 0; i < 16; i++) {
            int c = tid + i * 256;            // 0..4095
            int row = c >> 5, pos = c & 31;
            uint32_t off = (uint32_t)(row * 512 + ((pos ^ (row & 7)) << 4));
            cp16(sbase + off, g_Vhi + (size_t)(m0 + row) * NDIM + pos * 8);
        }
    }
    int b_row[4], b_pos[4]; uint32_t b_soff[4];
#pragma unroll
    for (int i = 0; i < 4; i++) {
        int c = tid + i * 256;                // 0..1023
        b_row[i] = c >> 3;
        b_pos[i] = c & 7;
        b_soff[i] = (uint32_t)(b_row[i] * 128 + ((b_pos[i] ^ (b_row[i] & 7)) << 4));
    }
    auto load_B = [&](int kt, int s) {
        int kk = kt * 64;
        uint32_t sB = sbase + SMEM_A_BYTES + (uint32_t)s * SMEM_B_STAGE;
#pragma unroll
        for (int i = 0; i < 4; i++)
            cp16(sB + b_soff[i], g_Ehi + (size_t)(n0g + b_row[i]) * NDIM + kk + b_pos[i] * 8);
        cp_commit();
    };
    load_B(0, 0);   // group 0 (with A)
    load_B(1, 1);   // group 1
    load_B(2, 2);   // group 2

    for (int kt = 0; kt < 4; kt++) {
        int s = kt % 3;
        if (kt <= 1) cp_wait<2>();
        else if (kt == 2) cp_wait<1>();
        else cp_wait<0>();
        __syncthreads();

        uint32_t sB = sbase + SMEM_A_BYTES + (uint32_t)s * SMEM_B_STAGE;
#pragma unroll
        for (int ks = 0; ks < 4; ks++) {
            uint32_t br[4][4];
#pragma unroll
            for (int nb = 0; nb < 4; nb++) {
                int n = wn * 64 + nb * 16 + (lane & 7) + ((lane >> 4) & 1) * 8;
                int chunk = ks * 2 + ((lane >> 3) & 1);
                ldsm_x4(br[nb], sB + (uint32_t)(n * 128 + ((chunk ^ (n & 7)) << 4)));
            }
            uint32_t ar[2][4];
#pragma unroll
            for (int mf = 0; mf < 2; mf++) {
                int row = wm * 32 + mf * 16 + (lane & 15);
                int chunk = kt * 8 + ks * 2 + (lane >> 4);
                ldsm_x4(ar[mf], sbase + (uint32_t)(row * 512 + ((chunk ^ (row & 7)) << 4)));
            }
#pragma unroll
            for (int mf = 0; mf < 2; mf++)
#pragma unroll
                for (int nb = 0; nb < 4; nb++) {
                    mma16816(acc[mf][nb * 2],     ar[mf], br[nb][0], br[nb][1]);
                    mma16816(acc[mf][nb * 2 + 1], ar[mf], br[nb][2], br[nb][3]);
                }
        }
        __syncthreads();
        if (kt == 0) load_B(3, 0);   // refill stage 0 with the last tile
    }

    // ---- fused epilogue: per-row L1, all-MUFU exp ----
#pragma unroll
    for (int mf = 0; mf < 2; mf++) {
#pragma unroll
        for (int half = 0; half < 2; half++) {
            float a1 = 0.f;
#pragma unroll
            for (int nf = 0; nf < 8; nf++) {
                a1 += exp2f(fmaf(acc[mf][nf][half * 2],     LOG2E, -SHIFT16_LOG2));
                a1 += exp2f(fmaf(acc[mf][nf][half * 2 + 1], LOG2E, -SHIFT16_LOG2));
            }
            a1 += __shfl_xor_sync(0xffffffffu, a1, 1);
            a1 += __shfl_xor_sync(0xffffffffu, a1, 2);
            if ((lane & 3) == 0) {
                int row = m0 + wm * 32 + mf * 16 + half * 8 + (lane >> 2);
                atomicAdd(&g_L1[row], a1);
            }
        }
    }
}

// ---------------- kernel 4: finalize, 8 blocks x 256 (1 row/thread) ---------
__global__ void finalize_kernel() {
    int r = blockIdx.x * 256 + threadIdx.x;
    int tid = threadIdx.x;
    float padL1 = (float)N_PAD_COLS * exp2f(-SHIFT16_LOG2);
    float L1 = g_L1[r] - padL1;
    float lse = 16.f + logf(L1);
    float dy = g_sy[r] - lse;
    float logp = fmaxf(dy, -100.f);
    float py = __expf(dy);
    float lm_y = fmaxf(log1pf(-py), -100.f);
    double acc = (double)(-1.f) + (double)logp - (double)lm_y;

    __shared__ double rd[256];
    rd[tid] = acc; __syncthreads();
    for (int o = 128; o > 0; o >>= 1) {
        if (tid < o) rd[tid] += rd[tid + o];
        __syncthreads();
    }
    if (tid == 0) atomicAdd(&g_acc, rd[0]);
}

// ---------------- kernel 5: write output ------------------------------------
__global__ void write_kernel(float* out) {
    out[0] = (float)(-g_acc * (1.0 / ((double)BSZ * (double)N_ENT)));
}

// ---------------- launch ----------------------------------------------------
extern "C" void kernel_launch(void* const* d_in, const int* in_sizes, int n_in,
                              void* d_out, int out_size) {
    const int*   facts = (const int*)d_in[0];
    const int*   arch  = (const int*)d_in[1];
    const float* ent_w = (const float*)d_in[2];
    const float* rel_w = (const float*)d_in[3];
    const float* bg_e  = (const float*)d_in[4];
    const float* bb_e  = (const float*)d_in[5];
    const float* bg_r  = (const float*)d_in[6];
    const float* bb_r  = (const float*)d_in[7];
    float* out = (float*)d_out;

    cudaFuncSetAttribute(gemm_kernel, cudaFuncAttributeMaxDynamicSharedMemorySize,
                         SMEM_TOTAL_GEMM);

    prep_kernel<<<CONV_BLOCKS + 768, 256>>>(facts, ent_w, rel_w, bg_e, bb_e, bg_r, bb_r);
    build_vec_kernel<<<BSZ, 256>>>(facts, arch, ent_w, rel_w);
    gemm_kernel<<<dim3(NPAD / 128, M_ROWS / 128), 256, SMEM_TOTAL_GEMM>>>();
    finalize_kernel<<<8, 256>>>();
    write_kernel<<<1, 1>>>(out);
}